// round 7
// baseline (speedup 1.0000x reference)
#include <cuda_runtime.h>

// LIF neuron recurrence, fully parallel across B*N neurons, serial over T.
//   out[t]  = (mem > 1.0f) ? 1 : 0
//   mem     = (0.5f*mem + syn) * (1 - out[t])
//   syn     = in[t]
// inputs: [T=100, B=256, N=2048] fp32 contiguous; output same shape.
//
// R7: burst-batch the memory streams. All prior configs plateau at ~6.0TB/s
// with fine-grained LDG/STG interleave (1 read + 1 write per step). Batch 4
// time steps: 4 back-to-back LDG.128 (2KB read run/warp), ALU-only recurrence
// for 4 steps, then 4 back-to-back STG.128 (2KB write run/warp) — 4x fewer
// DRAM read/write turnarounds. Config stays float4 512x256 (best measured).

constexpr int T_STEPS = 100;
constexpr int TB = 4;  // time-batch

__global__ void __launch_bounds__(256) lif_kernel(
    const float4* __restrict__ in,
    float4* __restrict__ out,
    int n4)
{
    int i = blockIdx.x * blockDim.x + threadIdx.x;
    if (i >= n4) return;

    float4 mem = make_float4(0.f, 0.f, 0.f, 0.f);
    float4 syn = make_float4(0.f, 0.f, 0.f, 0.f);

    size_t idx = (size_t)i;
    const size_t stride = (size_t)n4;

    #pragma unroll 1
    for (int t = 0; t < T_STEPS; t += TB) {
        // ---- read burst: 4 independent LDG.128 ----
        float4 x[TB];
        #pragma unroll
        for (int k = 0; k < TB; ++k)
            x[k] = in[idx + (size_t)k * stride];

        // ---- ALU-only recurrence for 4 steps ----
        float4 o[TB];
        #pragma unroll
        for (int k = 0; k < TB; ++k) {
            o[k].x = (mem.x > 1.0f) ? 1.0f : 0.0f;
            o[k].y = (mem.y > 1.0f) ? 1.0f : 0.0f;
            o[k].z = (mem.z > 1.0f) ? 1.0f : 0.0f;
            o[k].w = (mem.w > 1.0f) ? 1.0f : 0.0f;

            mem.x = (0.5f * mem.x + syn.x) * (1.0f - o[k].x);
            mem.y = (0.5f * mem.y + syn.y) * (1.0f - o[k].y);
            mem.z = (0.5f * mem.z + syn.z) * (1.0f - o[k].z);
            mem.w = (0.5f * mem.w + syn.w) * (1.0f - o[k].w);

            syn = x[k];
        }

        // ---- write burst: 4 back-to-back STG.128 ----
        #pragma unroll
        for (int k = 0; k < TB; ++k)
            out[idx + (size_t)k * stride] = o[k];

        idx += (size_t)TB * stride;
    }
}

extern "C" void kernel_launch(void* const* d_in, const int* in_sizes, int n_in,
                              void* d_out, int out_size)
{
    const float* in = (const float*)d_in[0];
    float* out = (float*)d_out;

    const int BN = in_sizes[0] / T_STEPS;  // 524288
    const int n4 = BN / 4;                 // 131072 float4 lanes

    const int threads = 256;
    const int blocks = (n4 + threads - 1) / threads;  // 512

    lif_kernel<<<blocks, threads>>>(
        (const float4*)in, (float4*)out, n4);
}